// round 13
// baseline (speedup 1.0000x reference)
#include <cuda_runtime.h>
#include <cstdint>

#define B_  4
#define Qn  1024
#define Kn  1024
#define QS  256
#define KSZ 256
#define Hn  32
#define VD  256
#define TQ  8
#define TK  128

// Device-global scratch (no runtime allocation allowed)
__device__ float g_fq[B_ * Qn * Hn];
__device__ float g_fk[B_ * Kn * Hn];

typedef unsigned long long u64;

// ---------------- helpers ----------------

__device__ __forceinline__ float fast_tanh(float x) {
    float y;
    asm("tanh.approx.f32 %0, %1;" : "=f"(y) : "f"(x));
    return y;
}

__device__ __forceinline__ float warp_sum(float v) {
    #pragma unroll
    for (int o = 16; o > 0; o >>= 1) v += __shfl_xor_sync(0xFFFFFFFFu, v, o);
    return v;
}

__device__ __forceinline__ u64 pack2(float lo, float hi) {
    u64 r;
    asm("mov.b64 %0, {%1, %2};" : "=l"(r) : "f"(lo), "f"(hi));
    return r;
}
__device__ __forceinline__ u64 add2(u64 a, u64 b) {
    u64 r;
    asm("add.rn.f32x2 %0, %1, %2;" : "=l"(r) : "l"(a), "l"(b));
    return r;
}
__device__ __forceinline__ void fma2(u64& a, u64 v, u64 p) {
    asm("fma.rn.f32x2 %0, %1, %2, %0;" : "+l"(a) : "l"(v), "l"(p));
}

__device__ __forceinline__ void cp_async16(unsigned int dst_smem, const void* src) {
    asm volatile("cp.async.ca.shared.global [%0], [%1], 16;" :: "r"(dst_smem), "l"(src));
}
__device__ __forceinline__ void cp_async_commit() {
    asm volatile("cp.async.commit_group;");
}
__device__ __forceinline__ void cp_async_wait0() {
    asm volatile("cp.async.wait_group 0;");
}

// ---------------- kernel 1: projections (unchanged from R12 — proven) ----------------

__global__ __launch_bounds__(128)
void proj_kernel(const float* __restrict__ queries, const float* __restrict__ keys,
                 const float* __restrict__ Wq, const float* __restrict__ bq,
                 const float* __restrict__ Wk, const float* __restrict__ bk,
                 const int* __restrict__ valid_lens) {
    __shared__ u64 part[4 * 2 * 8 * 16];    // [warp][rg][rowinoctet][hp] = 8KB

    const int tid  = threadIdx.x;
    const int w    = tid >> 5;
    const int lane = tid & 31;
    const int hp   = lane & 15;
    const int rg   = lane >> 4;
    const int rowbase_cta = blockIdx.x * 16;
    const int rowbase = rowbase_cta + rg * 8;

    const bool isQ = rowbase_cta < B_ * Qn;
    const float* srcbase; const u64* Wp; const u64* biasp; u64* dstbase;
    int valid = 0;
    if (isQ) {
        srcbase = queries; Wp = (const u64*)Wq; biasp = (const u64*)bq;
        dstbase = (u64*)g_fq;
    } else {
        int r2 = rowbase_cta - B_ * Qn;
        valid = valid_lens[r2 >> 10];
        if ((r2 & (Kn - 1)) >= valid) return;     // uniform across CTA
        srcbase = keys - (size_t)(B_ * Qn) * KSZ;
        Wp = (const u64*)Wk; biasp = (const u64*)bk;
        dstbase = (u64*)g_fk - (size_t)(B_ * Qn) * (Hn / 2);
    }

    const float4* s = (const float4*)(srcbase + (size_t)rowbase * QS);
    const int rstride = QS / 4;

    u64 acc[8];
    #pragma unroll
    for (int i = 0; i < 8; i++) acc[i] = 0ull;

    const int j40 = w * 16;
    #pragma unroll 4
    for (int jj = 0; jj < 16; jj++) {
        const int j4 = j40 + jj;
        const u64* wrow = Wp + (size_t)(4 * j4) * (Hn / 2) + hp;
        u64 w0 = __ldg(&wrow[0]);
        u64 w1 = __ldg(&wrow[Hn / 2]);
        u64 w2 = __ldg(&wrow[Hn]);
        u64 w3 = __ldg(&wrow[3 * Hn / 2]);
        #pragma unroll
        for (int i = 0; i < 8; i++) {
            float4 x = __ldg(&s[i * rstride + j4]);
            fma2(acc[i], pack2(x.x, x.x), w0);
            fma2(acc[i], pack2(x.y, x.y), w1);
            fma2(acc[i], pack2(x.z, x.z), w2);
            fma2(acc[i], pack2(x.w, x.w), w3);
        }
    }

    #pragma unroll
    for (int i = 0; i < 8; i++)
        part[((w * 2 + rg) * 8 + i) * 16 + hp] = acc[i];
    __syncthreads();

    u64 bias = __ldg(&biasp[tid & 15]);
    #pragma unroll
    for (int o = tid; o < 256; o += 128) {
        int row = o >> 4, h = o & 15;
        int ro = (row >> 3), ri = row & 7;
        u64 sum =      part[((0 * 2 + ro) * 8 + ri) * 16 + h];
        sum = add2(sum, part[((1 * 2 + ro) * 8 + ri) * 16 + h]);
        sum = add2(sum, part[((2 * 2 + ro) * 8 + ri) * 16 + h]);
        sum = add2(sum, part[((3 * 2 + ro) * 8 + ri) * 16 + h]);
        sum = add2(sum, bias);
        int grow = rowbase_cta + row;
        bool st = isQ || (((grow - B_ * Qn) & (Kn - 1)) < valid);
        if (st) dstbase[(size_t)grow * (Hn / 2) + h] = sum;
    }
}

// ---------------- transposed phase A (A-warps: w = 0..3) ----------------
// Warp w owns k-slice [32w, 32w+32) of the chunk; lane owns ONE k row.
// fk row (32 floats) lives in REGISTERS -> tile read exactly once per chunk.
// Computes p for ALL 8 q rows; accumulates l per (lane-k, q) in lacc regs.

__device__ __forceinline__ void phaseA_t(const float* fkbuf, u64* pdst,
                                         int kb, int valid, int w, int lane,
                                         const float* fq_sp, const float* wv_sp,
                                         float lacc[TQ]) {
    const int k = 32 * w + lane;
    const float4* fk4 = (const float4*)fkbuf;
    float4 f[8];
    #pragma unroll
    for (int j = 0; j < 8; j++) f[j] = fk4[k * 9 + j];

    float sc[TQ];
    #pragma unroll
    for (int q = 0; q < TQ; q++) sc[q] = 0.0f;

    const float4* fq4 = (const float4*)fq_sp;
    const float4* wv4 = (const float4*)wv_sp;

    #pragma unroll
    for (int hb = 0; hb < 8; hb++) {
        float4 g = wv4[hb];           // broadcast
        float4 fh = f[hb];            // register
        #pragma unroll
        for (int q = 0; q < TQ; q++) {
            float4 a = fq4[q * 8 + hb];   // broadcast
            sc[q] = fmaf(g.x, fast_tanh(a.x + fh.x), sc[q]);
            sc[q] = fmaf(g.y, fast_tanh(a.y + fh.y), sc[q]);
            sc[q] = fmaf(g.z, fast_tanh(a.z + fh.z), sc[q]);
            sc[q] = fmaf(g.w, fast_tanh(a.w + fh.w), sc[q]);
        }
    }

    const bool ok = (kb + k) < valid;
    ulonglong2* rowp = (ulonglong2*)(pdst + k * 10);
    #pragma unroll
    for (int qp = 0; qp < 4; qp++) {
        float p0 = ok ? __expf(sc[2 * qp])     : 0.0f;
        float p1 = ok ? __expf(sc[2 * qp + 1]) : 0.0f;
        lacc[2 * qp]     += p0;
        lacc[2 * qp + 1] += p1;
        ulonglong2 pair;
        pair.x = pack2(p0, p0);
        pair.y = pack2(p1, p1);
        rowp[qp] = pair;                 // STS.128, dup pairs
    }
}

// ---------------- kernel 2: fused additive attention ----------------
// grid = (B, Q/TQ), block = 256 (8 warps), 3 CTAs/SM.
// WARP SPECIALIZATION: warps 0-3 = phase A (tanh/exp, MUFU-heavy, fk in regs),
// warps 4-7 = phase B (P@V, LDG/FFMA2-heavy). Region c runs A(c+1) on A-warps
// and B(c) on B-warps concurrently (A writes pT2[bufA], B reads pT2[bufB]).
// No online softmax (|score| <= ||w_v||_1 since |tanh|<=1 -> exp safe in fp32).

__global__ __launch_bounds__(256, 3)
void attn_kernel(const float* __restrict__ values, const int* __restrict__ valid_lens,
                 const float* __restrict__ wvec, float* __restrict__ out) {
    __shared__ float fk_s[2][TK * 36];                   // [k][h], stride 36 floats
    __shared__ __align__(16) u64 pT2[2][TK * 10];        // [k][q] dup pair {p,p}, stride 10 u64
    __shared__ float fq_s[TQ * 32];
    __shared__ float wv_s[32];
    __shared__ float lpart_s[4 * TQ];                    // per-A-warp l partials

    const int tid  = threadIdx.x;
    const int w    = tid >> 5;
    const int lane = tid & 31;
    const int b    = blockIdx.x;
    const int q0   = blockIdx.y * TQ;
    const int valid = valid_lens[b];

    fq_s[w * 32 + lane] = g_fq[((size_t)(b * Qn + q0 + w)) * Hn + lane];
    if (tid < 32) wv_s[tid] = wvec[tid];

    float lacc[TQ];
    #pragma unroll
    for (int q = 0; q < TQ; q++) lacc[q] = 0.0f;

    u64 acc[TQ][2];                      // B-warps: 8q x 4 floats of (khalf, vhalf)
    #pragma unroll
    for (int q = 0; q < TQ; q++) { acc[q][0] = 0ull; acc[q][1] = 0ull; }

    const float* vbatch = values + (size_t)b * Kn * VD;
    const int nchunks = (valid + TK - 1) / TK;

    // ---- Preload fk(0) into buffer 0 (all threads) ----
    {
        const float4* src = (const float4*)(g_fk + ((size_t)(b * Kn)) * Hn);
        #pragma unroll
        for (int r = 0; r < 4; r++) {
            int idx = tid + 256 * r;
            unsigned int dst = (unsigned int)__cvta_generic_to_shared(
                &((float4*)fk_s[0])[(idx >> 3) * 9 + (idx & 7)]);
            cp_async16(dst, &src[idx]);
        }
        cp_async_commit();
        cp_async_wait0();
    }
    __syncthreads();

    // ---- Prologue: B-warps prefetch fk(1); A-warps compute A(0) ----
    if (w >= 4) {
        if (nchunks > 1) {
            const float4* src = (const float4*)(g_fk + ((size_t)(b * Kn + TK)) * Hn);
            const int t2 = tid - 128;
            #pragma unroll
            for (int r = 0; r < 8; r++) {
                int idx = t2 + 128 * r;
                unsigned int dst = (unsigned int)__cvta_generic_to_shared(
                    &((float4*)fk_s[1])[(idx >> 3) * 9 + (idx & 7)]);
                cp_async16(dst, &src[idx]);
            }
            cp_async_commit();
            cp_async_wait0();
        }
    } else {
        phaseA_t(fk_s[0], pT2[0], 0, valid, w, lane, fq_s, wv_s, lacc);
    }
    __syncthreads();

    // ---- Pipelined regions: region c = A(c+1) on w<4  ||  B(c) on w>=4 ----
    for (int c = 0; c < nchunks; c++) {
        const int kb   = c * TK;
        const int bufB = c & 1;
        const int bufA = bufB ^ 1;

        if (w >= 4) {
            // prefetch fk(c+2) into fk_s[bufB] (fk(c) is dead: A(c) done last region)
            if (c + 2 < nchunks) {
                const float4* src = (const float4*)(g_fk + ((size_t)(b * Kn + kb + 2 * TK)) * Hn);
                const int t2 = tid - 128;
                #pragma unroll
                for (int r = 0; r < 8; r++) {
                    int idx = t2 + 128 * r;
                    unsigned int dst = (unsigned int)__cvta_generic_to_shared(
                        &((float4*)fk_s[bufB])[(idx >> 3) * 9 + (idx & 7)]);
                    cp_async16(dst, &src[idx]);
                }
                cp_async_commit();
            }

            // -------- B(c): P@V. warp = (k-half (bw>>1)*64, v-half (bw&1)*128) --------
            const int bw    = w - 4;
            const int kloc0 = (bw >> 1) * 64;
            const int voff  = (bw & 1) * 128;
            const u64* pbase = pT2[bufB] + kloc0 * 10;
            const float* vb = vbatch + (size_t)(kb + kloc0) * VD + voff;

            int rem = valid - kb - kloc0;
            int kend = rem < 64 ? (rem < 0 ? 0 : rem) : 64;

            #pragma unroll 4
            for (int kk = 0; kk < kend; kk++) {
                ulonglong2 v = __ldg((const ulonglong2*)(vb + (size_t)kk * VD) + lane);
                const ulonglong2* prow2 = (const ulonglong2*)(pbase + kk * 10);
                #pragma unroll
                for (int qp = 0; qp < 4; qp++) {
                    ulonglong2 pp = prow2[qp];       // broadcast LDS.128
                    fma2(acc[2 * qp][0],     v.x, pp.x);
                    fma2(acc[2 * qp][1],     v.y, pp.x);
                    fma2(acc[2 * qp + 1][0], v.x, pp.y);
                    fma2(acc[2 * qp + 1][1], v.y, pp.y);
                }
            }

            if (c + 2 < nchunks) cp_async_wait0();
        } else {
            // -------- A(c+1): scores/exp for next chunk --------
            if (c + 1 < nchunks)
                phaseA_t(fk_s[bufA], pT2[bufA], kb + TK, valid, w, lane,
                         fq_s, wv_s, lacc);
        }
        __syncthreads();
    }

    // -------- Epilogue --------
    if (w < 4) {
        // A-warps: reduce l across the 32 lanes (each lane owned distinct k's)
        #pragma unroll
        for (int q = 0; q < TQ; q++) {
            float s = warp_sum(lacc[q]);
            if (lane == 0) lpart_s[w * TQ + q] = s;
        }
    } else {
        // B-warps: dump acc into smem: row (q*4 + bw) of 128 floats
        const int bw = w - 4;
        u64* bufu = (u64*)fk_s[0];       // 16KB scratch inside fk_s (18KB)
        #pragma unroll
        for (int q = 0; q < TQ; q++) {
            bufu[((q * 4 + bw) * 64) + lane * 2]     = acc[q][0];
            bufu[((q * 4 + bw) * 64) + lane * 2 + 1] = acc[q][1];
        }
    }
    __syncthreads();

    // All threads: out[q][v=tid] = (khalf0 + khalf1) / l
    {
        const float* buff = fk_s[0];
        const int vhalf = tid >> 7;
        const int idx   = tid & 127;
        const size_t obase = ((size_t)(b * Qn + q0)) * VD + tid;
        #pragma unroll
        for (int q = 0; q < TQ; q++) {
            float tot = buff[(q * 4 + vhalf) * 128 + idx]
                      + buff[(q * 4 + vhalf + 2) * 128 + idx];
            float l = lpart_s[q] + lpart_s[TQ + q] + lpart_s[2 * TQ + q] + lpart_s[3 * TQ + q];
            out[obase + (size_t)q * VD] = tot * (1.0f / l);
        }
    }
}

// ---------------- launch ----------------

extern "C" void kernel_launch(void* const* d_in, const int* in_sizes, int n_in,
                              void* d_out, int out_size) {
    const float* keys       = (const float*)d_in[0];
    const float* queries    = (const float*)d_in[1];
    const float* values     = (const float*)d_in[2];
    const int*   valid_lens = (const int*)d_in[3];
    const float* W_q        = (const float*)d_in[4];
    const float* b_q        = (const float*)d_in[5];
    const float* W_k        = (const float*)d_in[6];
    const float* b_k        = (const float*)d_in[7];
    const float* w_v        = (const float*)d_in[8];
    // b_v (d_in[9]) is softmax-invariant and intentionally unused.
    float* out = (float*)d_out;

    int total_rows = B_ * (Qn + Kn);            // 8192
    proj_kernel<<<total_rows / 16, 128>>>(queries, keys, W_q, b_q, W_k, b_k, valid_lens);

    dim3 grid(B_, Qn / TQ);
    attn_kernel<<<grid, 256>>>(values, valid_lens, w_v, out);
}